// round 1
// baseline (speedup 1.0000x reference)
#include <cuda_runtime.h>
#include <cstdint>
#include <cstddef>

// Problem constants
#define BSZ   64
#define NI    2048
#define DI    8
#define NO    32
#define DOUT  16

// Tiling
#define BT    32   // batches per CTA
#define NT    32   // input capsules per CTA
#define NTHREADS 512

// Scratch (static device globals: zero-initialized, no allocations)
__device__ float g_s[BSZ * NO * DOUT];      // 128 KB accumulator (always zero at launch entry)
__device__ float g_v[BSZ * NO * DOUT];      // 128 KB squashed output of previous iter
__device__ float g_blog[(size_t)BSZ * NI * NO]; // 16 MB routing logits (written pass1, read pass2)

__device__ __forceinline__ unsigned swz(unsigned byte_off) {
    // SW128-style: XOR bits[6:4] with bits[9:7] -> conflict-free LDS.128 of W tiles
    return byte_off ^ ((byte_off >> 3) & 0x70);
}

// One routing pass, fused with x_hat recomputation.
// PASS 0: c = 1/32 (softmax of zeros), accumulate s.
// PASS 1: b1 = v0 . x_hat  -> store b1, c = softmax(b1), accumulate s.
// PASS 2: b2 = b1 + v1 . x_hat, c = softmax(b2), accumulate s.
template <int PASS>
__global__ void __launch_bounds__(NTHREADS, 1)
caps_pass(const float* __restrict__ X, const float* __restrict__ W)
{
    extern __shared__ float sm[];
    float* x_s = sm;                       // BT*NT*DI   = 8192 floats
    float* w_s = x_s + BT * NT * DI;       // 4096 floats (swizzled W[n])
    float* v_s = w_s + 4096;               // BT*NO*DOUT = 16384 floats
    float* red = v_s + BT * NO * DOUT;     // 4 wg * 8 bi * 4 warps = 128 floats

    const int tid  = threadIdx.x;
    const int n0   = blockIdx.x * NT;
    const int b0   = blockIdx.y * BT;
    const int wg   = tid >> 7;      // warpgroup 0..3, handles 8 batches
    const int wt   = tid & 127;
    const int o    = wt >> 2;       // output capsule 0..31
    const int dg   = wt & 3;        // d-quad 0..3 (d = dg*4 + j)
    const int wiw  = (wt >> 5);     // warp within warpgroup 0..3
    const int lane = tid & 31;

    // Load x tile: [bb][nn][i], coalesced float4
#pragma unroll
    for (int it = 0; it < 4; it++) {
        int f = (it * NTHREADS + tid) * 4;
        int bb = f >> 8, rem = f & 255;  // 256 floats per batch row
        float4 t = *(const float4*)(X + (size_t)(b0 + bb) * (NI * DI) + n0 * DI + rem);
        *(float4*)(x_s + f) = t;
    }
    // Load v tile (previous iteration's output), contiguous
    if (PASS > 0) {
#pragma unroll
        for (int it = 0; it < 8; it++) {
            int f = (it * NTHREADS + tid) * 4;
            float4 t = *(const float4*)(g_v + (size_t)b0 * (NO * DOUT) + f);
            *(float4*)(v_s + f) = t;
        }
    }

    float sacc[8][4];
#pragma unroll
    for (int bi = 0; bi < 8; bi++)
#pragma unroll
        for (int j = 0; j < 4; j++) sacc[bi][j] = 0.0f;

    for (int nn = 0; nn < NT; nn++) {
        const int n = n0 + nn;
        __syncthreads();  // protect w_s reuse + (first iter) x_s/v_s visibility
        // Stage W[n] (4096 floats) into swizzled SMEM, coalesced
#pragma unroll
        for (int it = 0; it < 2; it++) {
            int flat = it * 2048 + tid * 4;
            float4 t = *(const float4*)(W + (size_t)n * 4096 + flat);
            *(float4*)((char*)w_s + swz((unsigned)flat * 4u)) = t;
        }
        __syncthreads();

        // Pull this thread's 32 W values (o fixed, d = dg*4+j, i = 0..7) into registers
        float wreg[32];
#pragma unroll
        for (int j = 0; j < 4; j++) {
            unsigned byt = (unsigned)(o * 128 + (dg * 4 + j) * 8) * 4u;
            float4 a = *(const float4*)((const char*)w_s + swz(byt));
            float4 b = *(const float4*)((const char*)w_s + swz(byt + 16));
            wreg[j * 8 + 0] = a.x; wreg[j * 8 + 1] = a.y;
            wreg[j * 8 + 2] = a.z; wreg[j * 8 + 3] = a.w;
            wreg[j * 8 + 4] = b.x; wreg[j * 8 + 5] = b.y;
            wreg[j * 8 + 6] = b.z; wreg[j * 8 + 7] = b.w;
        }

        // Prefetch routing logits for all 8 batches of this warpgroup (PASS 2)
        float blogpre[8];
        if (PASS == 2) {
#pragma unroll
            for (int bi = 0; bi < 8; bi++) {
                int bg = b0 + wg * 8 + bi;
                blogpre[bi] = g_blog[(size_t)bg * (NI * NO) + (size_t)n * NO + o];
            }
        }

#pragma unroll
        for (int bi = 0; bi < 8; bi++) {
            const int bloc = wg * 8 + bi;
            // x[b, n, 0..7] — broadcast LDS within the warpgroup
            const float* xp = x_s + (bloc * NT + nn) * DI;
            float4 xa = *(const float4*)(xp);
            float4 xb = *(const float4*)(xp + 4);
            float xr[8] = {xa.x, xa.y, xa.z, xa.w, xb.x, xb.y, xb.z, xb.w};

            // x_hat[o, dg*4 + j] = sum_i W[n,o,d,i] * x[b,n,i]
            float xh[4];
#pragma unroll
            for (int j = 0; j < 4; j++) {
                float a = 0.0f;
#pragma unroll
                for (int i = 0; i < 8; i++) a = fmaf(wreg[j * 8 + i], xr[i], a);
                xh[j] = a;
            }

            if (PASS == 0) {
#pragma unroll
                for (int j = 0; j < 4; j++)
                    sacc[bi][j] = fmaf(0.03125f, xh[j], sacc[bi][j]);  // c = 1/32
            } else {
                const int bglob = b0 + bloc;
                // t = v[b,o,:] . x_hat[b,n,o,:]  (partial over this thread's 4 d's)
                float4 vv = *(const float4*)(v_s + (bloc * NO + o) * DOUT + dg * 4);
                float t = xh[0] * vv.x + xh[1] * vv.y + xh[2] * vv.z + xh[3] * vv.w;
                t += __shfl_xor_sync(0xffffffffu, t, 1);
                t += __shfl_xor_sync(0xffffffffu, t, 2);   // full dot over 16 d

                if (PASS == 2) t += blogpre[bi];
                if (PASS == 1 && dg == 0)
                    g_blog[(size_t)bglob * (NI * NO) + (size_t)n * NO + o] = t;

                // softmax over o (logits are tiny; no max-subtraction needed)
                float e = __expf(t);
                float ws = e;
                ws += __shfl_xor_sync(0xffffffffu, ws, 4);
                ws += __shfl_xor_sync(0xffffffffu, ws, 8);
                ws += __shfl_xor_sync(0xffffffffu, ws, 16); // sum over this warp's 8 o's
                if (lane == 0) red[(wg * 8 + bi) * 4 + wiw] = ws;
                asm volatile("bar.sync %0, 128;" :: "r"(wg + 1) : "memory");
                const float* rp = red + (wg * 8 + bi) * 4;
                float tot = rp[0] + rp[1] + rp[2] + rp[3];
                float c = __fdividef(e, tot);
#pragma unroll
                for (int j = 0; j < 4; j++)
                    sacc[bi][j] = fmaf(c, xh[j], sacc[bi][j]);
            }
        }
    }

    // Fan partial s into global (64-way contention per address: negligible)
#pragma unroll
    for (int bi = 0; bi < 8; bi++) {
        int bglob = b0 + wg * 8 + bi;
        float* p = g_s + (size_t)bglob * (NO * DOUT) + o * DOUT + dg * 4;
#pragma unroll
        for (int j = 0; j < 4; j++) atomicAdd(p + j, sacc[bi][j]);
    }
}

// v = squash(s) = ||s||/(1+||s||^2) * s, per (b,o) row of 16.
// Also re-zeros g_s so every pass / graph replay starts clean.
__global__ void squash_k(float* __restrict__ extout)
{
    int idx = blockIdx.x * 256 + threadIdx.x;  // 32768 total
    float s = g_s[idx];
    float sq = s * s;
    sq += __shfl_xor_sync(0xffffffffu, sq, 1);
    sq += __shfl_xor_sync(0xffffffffu, sq, 2);
    sq += __shfl_xor_sync(0xffffffffu, sq, 4);
    sq += __shfl_xor_sync(0xffffffffu, sq, 8);   // ||s||^2 over 16 d
    float nrm = sqrtf(sq);
    float v = s * (nrm / (1.0f + sq));
    if (extout) extout[idx] = v;
    else        g_v[idx] = v;
    g_s[idx] = 0.0f;
}

extern "C" void kernel_launch(void* const* d_in, const int* in_sizes, int n_in,
                              void* d_out, int out_size)
{
    const float* X = (const float*)d_in[0];
    const float* W = (const float*)d_in[1];
    if (in_sizes[0] != BSZ * NI * DI) {  // defensive: identify x by element count
        X = (const float*)d_in[1];
        W = (const float*)d_in[0];
    }

    const size_t smem = (size_t)(BT * NT * DI + 4096 + BT * NO * DOUT + 128) * sizeof(float);
    cudaFuncSetAttribute(caps_pass<0>, cudaFuncAttributeMaxDynamicSharedMemorySize, (int)smem);
    cudaFuncSetAttribute(caps_pass<1>, cudaFuncAttributeMaxDynamicSharedMemorySize, (int)smem);
    cudaFuncSetAttribute(caps_pass<2>, cudaFuncAttributeMaxDynamicSharedMemorySize, (int)smem);

    dim3 grid(NI / NT, BSZ / BT);  // 64 x 2 = 128 CTAs

    caps_pass<0><<<grid, NTHREADS, smem>>>(X, W);
    squash_k<<<128, 256>>>((float*)nullptr);          // v0 -> g_v, zero g_s
    caps_pass<1><<<grid, NTHREADS, smem>>>(X, W);
    squash_k<<<128, 256>>>((float*)nullptr);          // v1 -> g_v, zero g_s
    caps_pass<2><<<grid, NTHREADS, smem>>>(X, W);
    squash_k<<<128, 256>>>((float*)d_out);            // v2 -> d_out, zero g_s
}